// round 6
// baseline (speedup 1.0000x reference)
#include <cuda_runtime.h>
#include <cuda_fp16.h>
#include <cstdint>

#define NE 16
#define DIN 128
#define HID 512
#define DOUT 64
#define BATCH 8192

// ---------------- device scratch (16B aligned for cp.async) ----------------
__device__ __align__(16) __half g_W1h[NE * HID * DIN];
__device__ __align__(16) __half g_W1l[NE * HID * DIN];
__device__ __align__(16) __half g_W2h[NE * HID * HID];
__device__ __align__(16) __half g_W2l[NE * HID * HID];
__device__ __align__(16) __half g_W3h[NE * DOUT * HID];
__device__ __align__(16) __half g_W3l[NE * DOUT * HID];
__device__ float g_part[(size_t)NE * BATCH * DOUT];

// ---------------- smem map (bytes) ----------------
#define SM_XH   0        // X / h2-chunk hi: 64 x stride136 (17408 B)
#define SM_XL   17408    // lo
#define SM_BUF0 34816    // weight buf0: hi 9216 + lo 9216
#define SM_BUF1 53248
#define SM_H1H  71680    // h1 hi: 64 x stride520 (66560 B)
#define SM_H1L  138240
#define SM_B1   204800
#define SM_B2   206848
#define SM_B3   208896
#define SMEM_SZ 209408

__device__ __forceinline__ uint32_t smem_u32(const void* p) {
    uint32_t a;
    asm("{ .reg .u64 t; cvta.to.shared.u64 t, %1; cvt.u32.u64 %0, t; }" : "=r"(a) : "l"(p));
    return a;
}
#define CP_COMMIT asm volatile("cp.async.commit_group;" ::: "memory")
#define CP_WAIT0  asm volatile("cp.async.wait_group 0;" ::: "memory")
#define CP_WAIT1  asm volatile("cp.async.wait_group 1;" ::: "memory")

__device__ __forceinline__ void mma16816(float* c, uint32_t a0, uint32_t a1, uint32_t a2,
                                         uint32_t a3, uint32_t b0, uint32_t b1) {
    asm volatile(
        "mma.sync.aligned.m16n8k16.row.col.f32.f16.f16.f32 "
        "{%0,%1,%2,%3},{%4,%5,%6,%7},{%8,%9},{%0,%1,%2,%3};"
        : "+f"(c[0]), "+f"(c[1]), "+f"(c[2]), "+f"(c[3])
        : "r"(a0), "r"(a1), "r"(a2), "r"(a3), "r"(b0), "r"(b1));
}

// load one weight panel [64n x 64k] hi+lo into buf (stride 72 halves = 144 B)
__device__ __forceinline__ void load_panel(uint32_t sb, uint32_t buf, const __half* sH,
                                           const __half* sL, int stride, int tid) {
#pragma unroll
    for (int i = 0; i < 2; i++) {
        int idx = tid + i * 256;
        int r = idx >> 3, j = idx & 7;
        uint32_t d = sb + buf + r * 144 + j * 16;
        const __half* pH = sH + (size_t)r * stride + j * 8;
        const __half* pL = sL + (size_t)r * stride + j * 8;
        asm volatile("cp.async.cg.shared.global [%0], [%1], 16;" :: "r"(d), "l"(pH));
        asm volatile("cp.async.cg.shared.global [%0], [%1], 16;" :: "r"(d + 9216), "l"(pL));
    }
}

// one K=64 panel of a 3-term GEMM: acc += Ah*Wh + Al*Wh + Ah*Wl
__device__ __forceinline__ void gemm_panel(const char* sm, uint32_t aH, int aLd, int astr,
                                           uint32_t wb, float* acc) {
#pragma unroll
    for (int k16 = 0; k16 < 4; k16++) {
        uint32_t o = aH + k16 * 32;
        uint32_t a0 = *(const uint32_t*)(sm + o);
        uint32_t a1 = *(const uint32_t*)(sm + o + astr * 8);
        uint32_t a2 = *(const uint32_t*)(sm + o + 16);
        uint32_t a3 = *(const uint32_t*)(sm + o + astr * 8 + 16);
        uint32_t l0 = *(const uint32_t*)(sm + o + aLd);
        uint32_t l1 = *(const uint32_t*)(sm + o + aLd + astr * 8);
        uint32_t l2 = *(const uint32_t*)(sm + o + aLd + 16);
        uint32_t l3 = *(const uint32_t*)(sm + o + aLd + astr * 8 + 16);
#pragma unroll
        for (int ns = 0; ns < 4; ns++) {
            uint32_t bo = wb + ns * 8 * 144 + k16 * 32;
            uint32_t b0 = *(const uint32_t*)(sm + bo);
            uint32_t b1 = *(const uint32_t*)(sm + bo + 16);
            uint32_t w0 = *(const uint32_t*)(sm + bo + 9216);
            uint32_t w1 = *(const uint32_t*)(sm + bo + 9216 + 16);
            mma16816(acc + ns * 4, a0, a1, a2, a3, b0, b1);
            mma16816(acc + ns * 4, l0, l1, l2, l3, b0, b1);
            mma16816(acc + ns * 4, a0, a1, a2, a3, w0, w1);
        }
    }
}

__device__ __forceinline__ void split_st(char* sm, uint32_t oh, int lod, float v0, float v1) {
    __half h0 = __float2half_rn(v0), h1 = __float2half_rn(v1);
    __half l0 = __float2half_rn(v0 - __half2float(h0));
    __half l1 = __float2half_rn(v1 - __half2float(h1));
    *(__half2*)(sm + oh) = __halves2half2(h0, h1);
    *(__half2*)(sm + oh + lod) = __halves2half2(l0, l1);
}

// relu(acc+bias) -> hi/lo fp16 at dstH (row stride strB bytes), lo at +lod
__device__ __forceinline__ void epi_relu(char* sm, uint32_t dstH, int lod, int strB,
                                         const float* bias, const float* acc,
                                         int r0, int cw) {
#pragma unroll
    for (int ns = 0; ns < 4; ns++) {
        int c = cw + ns * 8;
        float v00 = fmaxf(acc[ns * 4 + 0] + bias[c], 0.f);
        float v01 = fmaxf(acc[ns * 4 + 1] + bias[c + 1], 0.f);
        float v10 = fmaxf(acc[ns * 4 + 2] + bias[c], 0.f);
        float v11 = fmaxf(acc[ns * 4 + 3] + bias[c + 1], 0.f);
        split_st(sm, dstH + r0 * strB + c * 2, lod, v00, v01);
        split_st(sm, dstH + (r0 + 8) * strB + c * 2, lod, v10, v11);
    }
}

// ---------------- prologue: transpose + fp16 hi/lo split ----------------
__global__ void tsplit(const float* __restrict__ src, int which, int K, int N) {
    __shared__ float t[32][33];
    __half *dh, *dl;
    if (which == 0) { dh = g_W1h; dl = g_W1l; }
    else if (which == 1) { dh = g_W2h; dl = g_W2l; }
    else { dh = g_W3h; dl = g_W3l; }
    int e = blockIdx.z, k0 = blockIdx.x * 32, n0 = blockIdx.y * 32;
    int tx = threadIdx.x, ty = threadIdx.y;
    const float* s = src + (size_t)e * K * N;
#pragma unroll
    for (int i = 0; i < 32; i += 8)
        t[ty + i][tx] = s[(size_t)(k0 + ty + i) * N + n0 + tx];
    __syncthreads();
#pragma unroll
    for (int i = 0; i < 32; i += 8) {
        float v = t[tx][ty + i];
        __half h = __float2half_rn(v);
        size_t o = (size_t)e * N * K + (size_t)(n0 + ty + i) * K + k0 + tx;
        dh[o] = h;
        dl[o] = __float2half_rn(v - __half2float(h));
    }
}

// ---------------- main fused kernel ----------------
__global__ void __launch_bounds__(256, 1)
moe_main(const float* __restrict__ x, const float* __restrict__ b1,
         const float* __restrict__ b2, const float* __restrict__ b3) {
    extern __shared__ char sm[];
    const int tid = threadIdx.x, wid = tid >> 5, lid = tid & 31;
    const int g = lid >> 2, t = lid & 3;
    const int wR = wid & 3, wC = wid >> 2;       // 4 x 2 warp grid over 64x64
    const int m0 = blockIdx.x * 64, e = blockIdx.y;
    const uint32_t sb = smem_u32(sm);

    float* b1s = (float*)(sm + SM_B1);
    float* b2s = (float*)(sm + SM_B2);
    float* b3s = (float*)(sm + SM_B3);
    for (int i = tid; i < HID; i += 256) {
        b1s[i] = b1[e * HID + i];
        b2s[i] = b2[e * HID + i];
    }
    if (tid < DOUT) b3s[tid] = b3[e * DOUT + tid];

    // X tile [64 x 128] -> fp16 hi/lo, padded stride 136 halves
    for (int i = tid; i < 2048; i += 256) {
        int r = i >> 5, j = i & 31;
        float4 f = ((const float4*)(x + ((size_t)(m0 + r) * NE + e) * DIN))[j];
        uint32_t o = (uint32_t)(r * 136 + j * 4) * 2;
        split_st(sm, SM_XH + o, SM_XL - SM_XH, f.x, f.y);
        split_st(sm, SM_XH + o + 4, SM_XL - SM_XH, f.z, f.w);
    }
    __syncthreads();

    const uint32_t aX = (uint32_t)(((wR * 16 + g) * 136 + t * 2) * 2);           // stride 272B
    const uint32_t aH1 = SM_H1H + (uint32_t)(((wR * 16 + g) * 520 + t * 2) * 2); // stride 1040B
    const uint32_t aH2 = (uint32_t)(((wR * 16 + g) * 72 + t * 2) * 2);           // stride 144B
    const uint32_t wbB0 = SM_BUF0 + (uint32_t)(((wC * 32 + g) * 72 + t * 2) * 2);
    const uint32_t wbB1 = SM_BUF1 + (uint32_t)(((wC * 32 + g) * 72 + t * 2) * 2);
    const int r0 = wR * 16 + g, cw = wC * 32 + t * 2;

    float acc[16];

    // ---- phase 1: h1 = relu(X @ W1 + b1), 8 chunks of 64 cols ----
    for (int nc = 0; nc < 8; nc++) {
        const __half* w1h = g_W1h + ((size_t)e * HID + nc * 64) * DIN;
        const __half* w1l = g_W1l + ((size_t)e * HID + nc * 64) * DIN;
#pragma unroll
        for (int i = 0; i < 16; i++) acc[i] = 0.f;
        load_panel(sb, SM_BUF0, w1h, w1l, DIN, tid); CP_COMMIT;
        load_panel(sb, SM_BUF1, w1h + 64, w1l + 64, DIN, tid); CP_COMMIT;
        CP_WAIT1; __syncthreads();
        gemm_panel(sm, aX, SM_XL - SM_XH, 272, wbB0, acc);
        CP_WAIT0; __syncthreads();
        gemm_panel(sm, aX + 128, SM_XL - SM_XH, 272, wbB1, acc);
        __syncthreads();
        // FIX (R3): h1 chunk nc lives at columns nc*64 (= nc*128 bytes)
        epi_relu(sm, SM_H1H + nc * 128, SM_H1L - SM_H1H, 1040, b1s + nc * 64, acc, r0, cw);
    }
    __syncthreads();

    // ---- phase 2: h2 chunks + layer-3 accumulation ----
    float out[16];
#pragma unroll
    for (int i = 0; i < 16; i++) out[i] = 0.f;

    for (int nc = 0; nc < 8; nc++) {
        const __half* w2h = g_W2h + ((size_t)e * HID + nc * 64) * HID;
        const __half* w2l = g_W2l + ((size_t)e * HID + nc * 64) * HID;
        const __half* w3h = g_W3h + (size_t)e * DOUT * HID + nc * 64;
        const __half* w3l = g_W3l + (size_t)e * DOUT * HID + nc * 64;
#pragma unroll
        for (int i = 0; i < 16; i++) acc[i] = 0.f;
        load_panel(sb, SM_BUF0, w2h, w2l, HID, tid); CP_COMMIT;
        for (int p = 0; p < 8; p++) {
            uint32_t nb = ((p + 1) & 1) ? SM_BUF1 : SM_BUF0;
            if (p < 7) load_panel(sb, nb, w2h + (p + 1) * 64, w2l + (p + 1) * 64, HID, tid);
            else       load_panel(sb, nb, w3h, w3l, HID, tid);
            CP_COMMIT;
            CP_WAIT1; __syncthreads();
            gemm_panel(sm, aH1 + p * 128, SM_H1L - SM_H1H, 1040,
                       (p & 1) ? wbB1 : wbB0, acc);
            __syncthreads();
        }
        // h2 chunk -> X region (stride 144B)
        epi_relu(sm, SM_XH, SM_XL - SM_XH, 144, b2s + nc * 64, acc, r0, cw);
        CP_WAIT0; __syncthreads();
        gemm_panel(sm, aH2, SM_XL - SM_XH, 144, wbB0, out);
        __syncthreads();
    }

    // ---- phase 3: write partial [e][m][64] ----
    float* dst = g_part + ((size_t)e * BATCH + m0) * DOUT;
#pragma unroll
    for (int ns = 0; ns < 4; ns++) {
        int c = cw + ns * 8;
        float2 v0 = make_float2(out[ns * 4 + 0] + b3s[c], out[ns * 4 + 1] + b3s[c + 1]);
        float2 v1 = make_float2(out[ns * 4 + 2] + b3s[c], out[ns * 4 + 3] + b3s[c + 1]);
        *(float2*)(dst + (size_t)r0 * DOUT + c) = v0;
        *(float2*)(dst + (size_t)(r0 + 8) * DOUT + c) = v1;
    }
}

// ---------------- deterministic expert reduction ----------------
__global__ void reduce_out(float* __restrict__ out) {
    int i = blockIdx.x * blockDim.x + threadIdx.x;
    float s = 0.f;
#pragma unroll
    for (int e = 0; e < NE; e++) s += g_part[(size_t)e * BATCH * DOUT + i];
    out[i] = s;
}

// ---------------- launcher ----------------
extern "C" void kernel_launch(void* const* d_in, const int* in_sizes, int n_in,
                              void* d_out, int out_size) {
    const float* x  = (const float*)d_in[0];
    const float* W1 = (const float*)d_in[1];
    const float* b1 = (const float*)d_in[2];
    const float* W2 = (const float*)d_in[3];
    const float* b2 = (const float*)d_in[4];
    const float* W3 = (const float*)d_in[5];
    const float* b3 = (const float*)d_in[6];
    float* out = (float*)d_out;

    cudaFuncSetAttribute(moe_main, cudaFuncAttributeMaxDynamicSharedMemorySize, SMEM_SZ);

    dim3 t32(32, 8);
    tsplit<<<dim3(DIN / 32, HID / 32, NE), t32>>>(W1, 0, DIN, HID);
    tsplit<<<dim3(HID / 32, HID / 32, NE), t32>>>(W2, 1, HID, HID);
    tsplit<<<dim3(HID / 32, DOUT / 32, NE), t32>>>(W3, 2, HID, DOUT);

    moe_main<<<dim3(BATCH / 64, NE), 256, SMEM_SZ>>>(x, b1, b2, b3);

    reduce_out<<<(BATCH * DOUT) / 256, 256>>>(out);
}